// round 7
// baseline (speedup 1.0000x reference)
#include <cuda_runtime.h>
#include <stdint.h>
#include <math.h>

#define THREADS 256
#define BATCH 32
#define SPIX (768*768)            // 589824 pixels per sample
#define S2 (SPIX/2)               // 294912 2-pixel units per sample
#define NPAIR (BATCH*2)           // 64 (sample, channel) pairs
#define NBINS 4096
#define CHUNK 9216                // pixels per block
#define J_PER_BLK (CHUNK/2)       // 4608 2-pixel units per block (= 18*256)
#define BLOCKS_PER_SAMPLE (SPIX/CHUNK)   // 64
#define NBLOCKS (BATCH*BLOCKS_PER_SAMPLE) // 2048
#define P1_BLOCKS (NBLOCKS/8)     // 256: sample 1/8 of chunks in pass1
#define POS_THR 0.1f

// ---------------- scratch (static __device__, no allocations) ----------------
__device__ unsigned int g_pos_cnt[NPAIR];    // sampled (1/8) positive counts
__device__ unsigned int g_pos_cnt2[NPAIR];   // exact positive counts (pass2)
__device__ unsigned int g_s_hist[NPAIR*NBINS];
__device__ unsigned int g_lo_key[NPAIR];
__device__ unsigned int g_hi_key[NPAIR];
__device__ int          g_shift[NPAIR];
__device__ unsigned int g_above_cnt[NPAIR];
__device__ double       g_above_sum[NPAIR];
__device__ double       g_pos_sum[NPAIR];
__device__ unsigned int g_h2_cnt[NPAIR*NBINS];
__device__ float        g_h2_sum[NPAIR*NBINS];

// ---------------- reductions ----------------
__device__ __forceinline__ float blockSumF(float v, volatile float* sh) {
#pragma unroll
    for (int o = 16; o; o >>= 1) v += __shfl_down_sync(0xFFFFFFFFu, v, o);
    int w = threadIdx.x >> 5;
    __syncthreads();
    if ((threadIdx.x & 31) == 0) sh[w] = v;
    __syncthreads();
    float r = (threadIdx.x < 8) ? sh[threadIdx.x] : 0.f;
    if (threadIdx.x < 32) {
#pragma unroll
        for (int o = 4; o; o >>= 1) r += __shfl_down_sync(0xFFFFFFFFu, r, o);
    }
    return r;
}

__device__ __forceinline__ int blockSumI(int v, volatile int* sh) {
#pragma unroll
    for (int o = 16; o; o >>= 1) v += __shfl_down_sync(0xFFFFFFFFu, v, o);
    int w = threadIdx.x >> 5;
    __syncthreads();
    if ((threadIdx.x & 31) == 0) sh[w] = v;
    __syncthreads();
    int r = (threadIdx.x < 8) ? sh[threadIdx.x] : 0;
    if (threadIdx.x < 32) {
#pragma unroll
        for (int o = 4; o; o >>= 1) r += __shfl_down_sync(0xFFFFFFFFu, r, o);
    }
    return r;
}

// ---------------- kernel 0: zero scratch + output ----------------
__global__ void k_zero(float* out) {
    int i = blockIdx.x * blockDim.x + threadIdx.x;
    if (i < NPAIR * NBINS) {
        g_s_hist[i] = 0u;
        g_h2_cnt[i] = 0u;
        g_h2_sum[i] = 0.f;
    }
    if (i < NPAIR) {
        g_pos_cnt[i] = 0u;
        g_pos_cnt2[i] = 0u;
        g_above_cnt[i] = 0u;
        g_above_sum[i] = 0.0;
        g_pos_sum[i] = 0.0;
    }
    if (i == 0) out[0] = 0.f;
}

// ---------------- kernel 1: sampled pos counts + sampled negative histogram ----------------
// 256 blocks = 1/8 of chunks. Labels of sampled chunks read fully (p sampled at 1/8);
// pred read every 3rd unit-iter (histogram samples 1/24 of pixels).
__global__ void __launch_bounds__(THREADS) k_pass1(
    const float4* __restrict__ pred4,
    const float2* __restrict__ reg2,
    const float2* __restrict__ aff2)
{
    int blk = blockIdx.x;
    int s = blk >> 3;                 // 8 sampled chunks per sample
    int ci = (blk & 7) << 3;          // chunks 0,8,16,...,56
    int base = s * S2 + ci * J_PER_BLK;
    int tid = threadIdx.x;

    unsigned int* h0 = g_s_hist + (2 * s) * NBINS;
    unsigned int* h1 = g_s_hist + (2 * s + 1) * NBINS;

    int c0 = 0, c1 = 0;
    for (int g = 0; g < 3; ++g) {
        float2 rg[6], af[6];
        int idx = base + (g * 6) * THREADS + tid;
#pragma unroll
        for (int j = 0; j < 6; ++j) {
            rg[j] = __ldcs(&reg2[idx + j * THREADS]);
            af[j] = __ldcs(&aff2[idx + j * THREADS]);
        }
        float4 pr0 = __ldcs(&pred4[idx]);
        float4 pr3 = __ldcs(&pred4[idx + 3 * THREADS]);
#pragma unroll
        for (int j = 0; j < 6; ++j) {
            c0 += (rg[j].x >= POS_THR) + (rg[j].y >= POS_THR);
            c1 += (af[j].x >= POS_THR) + (af[j].y >= POS_THR);
        }
        float d;
        if (rg[0].x < POS_THR) { d = pr0.x - rg[0].x; float l = d * d; atomicAdd(&h0[__float_as_uint(l) >> 20], 1u); }
        if (af[0].x < POS_THR) { d = pr0.y - af[0].x; float l = d * d; atomicAdd(&h1[__float_as_uint(l) >> 20], 1u); }
        if (rg[0].y < POS_THR) { d = pr0.z - rg[0].y; float l = d * d; atomicAdd(&h0[__float_as_uint(l) >> 20], 1u); }
        if (af[0].y < POS_THR) { d = pr0.w - af[0].y; float l = d * d; atomicAdd(&h1[__float_as_uint(l) >> 20], 1u); }
        if (rg[3].x < POS_THR) { d = pr3.x - rg[3].x; float l = d * d; atomicAdd(&h0[__float_as_uint(l) >> 20], 1u); }
        if (af[3].x < POS_THR) { d = pr3.y - af[3].x; float l = d * d; atomicAdd(&h1[__float_as_uint(l) >> 20], 1u); }
        if (rg[3].y < POS_THR) { d = pr3.z - rg[3].y; float l = d * d; atomicAdd(&h0[__float_as_uint(l) >> 20], 1u); }
        if (af[3].y < POS_THR) { d = pr3.w - af[3].y; float l = d * d; atomicAdd(&h1[__float_as_uint(l) >> 20], 1u); }
    }
    __shared__ int shi[8];
    int t0 = blockSumI(c0, shi);
    if (tid == 0 && t0) atomicAdd(&g_pos_cnt[2 * s], (unsigned)t0);
    int t1 = blockSumI(c1, shi);
    if (tid == 0 && t1) atomicAdd(&g_pos_cnt[2 * s + 1], (unsigned)t1);
}

// ---------------- kernel 2: pick bracket [lo_key, hi_key) from sample ----------------
__global__ void __launch_bounds__(THREADS) k_select()
{
    int pair = blockIdx.x;
    int tid = threadIdx.x;
    const unsigned int* h = g_s_hist + pair * NBINS;

    unsigned lc[16]; unsigned cnt = 0;
#pragma unroll
    for (int i = 0; i < 16; ++i) { lc[i] = h[NBINS - 1 - (tid * 16 + i)]; cnt += lc[i]; }

    __shared__ unsigned scnt[THREADS];
    scnt[tid] = cnt; __syncthreads();
    for (int off = 1; off < THREADS; off <<= 1) {
        unsigned c2 = (tid >= off) ? scnt[tid - off] : 0u;
        __syncthreads();
        scnt[tid] += c2;
        __syncthreads();
    }

    __shared__ long long sh_hi_r, sh_lo_r;
    __shared__ int sh_hb, sh_lb, sh_kpos;
    if (tid == 0) {
        double p_hat = 8.0 * (double)g_pos_cnt[pair];       // labels sampled at 1/8
        double nn_hat = (double)SPIX - p_hat;
        if (nn_hat < 1.0) nn_hat = 1.0;
        long long m = (long long)scnt[THREADS - 1];
        long long hi_r = 1, lo_r = (m > 0) ? m : 1;
        int kpos = 1;
        if (m > 0) {
            double scale = nn_hat / (double)m;              // ~24
            if (p_hat < 10000.0) {
                double k_up = 3.0 * (p_hat + 8.0 * sqrt(7.0 * p_hat + 1.0) + 300.0);
                if (k_up < 500.0) k_up = 500.0;
                double lr = k_up / scale + 8.0 * sqrt(0.25 * (double)m) + 192.0;
                hi_r = 1;
                lo_r = (lr >= (double)m) ? m : (long long)(lr + 1.0);
            } else {
                double k_hat = 3.0 * p_hat;
                if (k_hat > nn_hat) k_hat = nn_hat;
                double ks = k_hat / scale;                  // target sample rank
                double delta = 16.0 * sqrt(p_hat) / scale   // sampled-p uncertainty
                             + 8.0 * sqrt(0.25 * (double)m) // sample-rank noise
                             + 192.0;
                double a = ks - delta, b2 = ks + delta;
                hi_r = (a < 1.0) ? 1 : (long long)a;
                lo_r = (b2 >= (double)m) ? m : (long long)(b2 + 1.0);
                if (lo_r < hi_r) lo_r = hi_r;
            }
        } else {
            kpos = 0;
        }
        sh_hi_r = hi_r; sh_lo_r = lo_r; sh_kpos = kpos;
        sh_hb = NBINS - 1; sh_lb = 0;
    }
    __syncthreads();
    long long hi_r = sh_hi_r, lo_r = sh_lo_r;
    long long ex = (long long)(scnt[tid] - cnt), inc = (long long)scnt[tid];
    if (ex < hi_r && hi_r <= inc) {
        long long cc = ex;
#pragma unroll
        for (int i = 0; i < 16; ++i) { cc += lc[i]; if (hi_r <= cc) { sh_hb = NBINS - 1 - (tid * 16 + i); break; } }
    }
    if (ex < lo_r && lo_r <= inc) {
        long long cc = ex;
#pragma unroll
        for (int i = 0; i < 16; ++i) { cc += lc[i]; if (lo_r <= cc) { sh_lb = NBINS - 1 - (tid * 16 + i); break; } }
    }
    __syncthreads();
    if (tid == 0) {
        unsigned lo_key; unsigned long long hk; int sft = 8;
        if (sh_kpos) {
            int hi_bin = sh_hb + 3; if (hi_bin > NBINS - 1) hi_bin = NBINS - 1;
            int lo_bin = sh_lb - 3; if (lo_bin < 0) lo_bin = 0;
            if (lo_bin > hi_bin) lo_bin = hi_bin;
            int span = hi_bin - lo_bin + 1;
            while (((long long)span << 20) > (4096LL << sft)) sft++;
            lo_key = ((unsigned)lo_bin) << 20;
            hk = (unsigned long long)lo_key + (4096ULL << sft);
            if (hk > 0x7F800000ULL) hk = 0x7F800000ULL;
        } else {
            lo_key = 0u; hk = 0ULL;   // no sampled negatives: everything "above"
        }
        g_lo_key[pair] = lo_key;
        g_hi_key[pair] = (unsigned)hk;
        g_shift[pair] = sft;
    }
}

// ---------------- kernel 3: full pass ----------------
__device__ __forceinline__ void proc_px(float pc, float lab,
    unsigned lo, unsigned hi, int sft,
    float& psum, int& pcn, float& asum, int& acnt,
    unsigned* __restrict__ hcnt, float* __restrict__ hsum)
{
    float d = pc - lab;
    float l = d * d;
    if (lab >= POS_THR) {
        pcn++;
        psum += l;
    } else {
        unsigned u = __float_as_uint(l);
        if (u >= hi) { acnt++; asum += l; }
        else if (u >= lo) {
            unsigned b = (u - lo) >> sft;
            if (b > 4095u) b = 4095u;
            atomicAdd(hcnt + b, 1u);
            atomicAdd(hsum + b, l);
        }
    }
}

__global__ void __launch_bounds__(THREADS) k_pass2(
    const float4* __restrict__ pred4,
    const float2* __restrict__ reg2,
    const float2* __restrict__ aff2)
{
    int blk = blockIdx.x;
    int s = blk / BLOCKS_PER_SAMPLE;
    int chunk = blk - s * BLOCKS_PER_SAMPLE;
    int base = s * S2 + chunk * J_PER_BLK;
    int tid = threadIdx.x;

    unsigned lo0 = g_lo_key[2 * s], hi0 = g_hi_key[2 * s]; int sf0 = g_shift[2 * s];
    unsigned lo1 = g_lo_key[2 * s + 1], hi1 = g_hi_key[2 * s + 1]; int sf1 = g_shift[2 * s + 1];
    unsigned* hc0 = g_h2_cnt + (2 * s) * NBINS;     float* hs0 = g_h2_sum + (2 * s) * NBINS;
    unsigned* hc1 = g_h2_cnt + (2 * s + 1) * NBINS; float* hs1 = g_h2_sum + (2 * s + 1) * NBINS;

    float ps0 = 0.f, ps1 = 0.f, as0 = 0.f, as1 = 0.f;
    int ac0 = 0, ac1 = 0, pc0 = 0, pc1 = 0;

    // 18 unit-steps = 3 groups of 6; all 18 vector loads of a group issued
    // before any consumption (MLP ~= 1.5KB in flight per warp).
    for (int g = 0; g < 3; ++g) {
        float4 pr[6]; float2 rg[6], af[6];
        int idx = base + (g * 6) * THREADS + tid;
#pragma unroll
        for (int j = 0; j < 6; ++j) pr[j] = __ldcs(&pred4[idx + j * THREADS]);
#pragma unroll
        for (int j = 0; j < 6; ++j) rg[j] = __ldcs(&reg2[idx + j * THREADS]);
#pragma unroll
        for (int j = 0; j < 6; ++j) af[j] = __ldcs(&aff2[idx + j * THREADS]);
#pragma unroll
        for (int j = 0; j < 6; ++j) {
            proc_px(pr[j].x, rg[j].x, lo0, hi0, sf0, ps0, pc0, as0, ac0, hc0, hs0);
            proc_px(pr[j].y, af[j].x, lo1, hi1, sf1, ps1, pc1, as1, ac1, hc1, hs1);
            proc_px(pr[j].z, rg[j].y, lo0, hi0, sf0, ps0, pc0, as0, ac0, hc0, hs0);
            proc_px(pr[j].w, af[j].y, lo1, hi1, sf1, ps1, pc1, as1, ac1, hc1, hs1);
        }
    }

    __shared__ float shf[8];
    __shared__ int shi[8];
    float t;
    t = blockSumF(ps0, shf); if (tid == 0 && t != 0.f) atomicAdd(&g_pos_sum[2 * s], (double)t);
    t = blockSumF(ps1, shf); if (tid == 0 && t != 0.f) atomicAdd(&g_pos_sum[2 * s + 1], (double)t);
    t = blockSumF(as0, shf); if (tid == 0 && t != 0.f) atomicAdd(&g_above_sum[2 * s], (double)t);
    t = blockSumF(as1, shf); if (tid == 0 && t != 0.f) atomicAdd(&g_above_sum[2 * s + 1], (double)t);
    int ti;
    ti = blockSumI(ac0, shi); if (tid == 0 && ti) atomicAdd(&g_above_cnt[2 * s], (unsigned)ti);
    ti = blockSumI(ac1, shi); if (tid == 0 && ti) atomicAdd(&g_above_cnt[2 * s + 1], (unsigned)ti);
    ti = blockSumI(pc0, shi); if (tid == 0 && ti) atomicAdd(&g_pos_cnt2[2 * s], (unsigned)ti);
    ti = blockSumI(pc1, shi); if (tid == 0 && ti) atomicAdd(&g_pos_cnt2[2 * s + 1], (unsigned)ti);
}

// ---------------- kernel 4: resolve threshold bin, produce final scalar ----------------
__global__ void __launch_bounds__(THREADS) k_final(float* out)
{
    int pair = blockIdx.x;
    int tid = threadIdx.x;
    const unsigned* hc = g_h2_cnt + pair * NBINS;
    const float* hs = g_h2_sum + pair * NBINS;

    unsigned lc[16]; float lsv[16];
    unsigned cnt = 0; float fsum = 0.f;
#pragma unroll
    for (int i = 0; i < 16; ++i) {
        int b = NBINS - 1 - (tid * 16 + i);
        lc[i] = hc[b]; lsv[i] = hs[b];
        cnt += lc[i]; fsum += lsv[i];
    }
    __shared__ unsigned long long scnt[THREADS];
    __shared__ double ssum[THREADS];
    scnt[tid] = cnt; ssum[tid] = (double)fsum;
    __syncthreads();
    for (int off = 1; off < THREADS; off <<= 1) {
        unsigned long long c2 = 0; double s2 = 0;
        if (tid >= off) { c2 = scnt[tid - off]; s2 = ssum[tid - off]; }
        __syncthreads();
        scnt[tid] += c2; ssum[tid] += s2;
        __syncthreads();
    }

    long long p = (long long)g_pos_cnt2[pair];           // exact
    long long nn = (long long)SPIX - p;
    long long k = (p > 0) ? ((nn < 3 * p) ? nn : 3 * p) : 500LL;
    if (k > nn) k = nn;
    if (k < 0) k = 0;

    long long above = (long long)g_above_cnt[pair];
    double above_sum = g_above_sum[pair];
    long long r = k - above;
    long long total = (long long)scnt[THREADS - 1];

    __shared__ double res;
    if (tid == 0) {
        if (r <= 0) res = (above > 0) ? above_sum * (double)k / (double)above : 0.0;
        else if (r > total) res = above_sum + ssum[THREADS - 1];
    }
    if (r > 0 && r <= total) {
        long long ex = (long long)(scnt[tid] - cnt);
        if (ex < r && r <= (long long)scnt[tid]) {
            long long cc = ex;
            double ss = ssum[tid] - (double)fsum;
#pragma unroll
            for (int i = 0; i < 16; ++i) {
                if (r <= cc + (long long)lc[i]) {
                    double avg = lc[i] ? (double)lsv[i] / (double)lc[i] : 0.0;
                    res = above_sum + ss + (double)(r - cc) * avg;
                    break;
                }
                cc += lc[i]; ss += (double)lsv[i];
            }
        }
    }
    __syncthreads();
    if (tid == 0) {
        double nega = (k > 0) ? res / (double)k : 0.0;
        double posi = (p > 0) ? g_pos_sum[pair] / (double)p : 0.0;
        atomicAdd(out, (float)((posi + nega) / (double)BATCH));
    }
}

// ---------------- launcher ----------------
extern "C" void kernel_launch(void* const* d_in, const int* in_sizes, int n_in,
                              void* d_out, int out_size)
{
    const int predN = BATCH * SPIX * 2;
    const float* pred = nullptr;
    const float* reg = nullptr;
    const float* aff = nullptr;
    for (int i = 0; i < n_in; i++) {
        if (in_sizes[i] == predN && !pred) pred = (const float*)d_in[i];
        else if (!reg) reg = (const float*)d_in[i];
        else if (!aff) aff = (const float*)d_in[i];
    }
    float* out = (float*)d_out;

    k_zero<<<(NPAIR * NBINS + THREADS - 1) / THREADS, THREADS>>>(out);
    k_pass1<<<P1_BLOCKS, THREADS>>>((const float4*)pred, (const float2*)reg, (const float2*)aff);
    k_select<<<NPAIR, THREADS>>>();
    k_pass2<<<NBLOCKS, THREADS>>>((const float4*)pred, (const float2*)reg, (const float2*)aff);
    k_final<<<NPAIR, THREADS>>>(out);
}

// round 8
// speedup vs baseline: 1.0493x; 1.0493x over previous
#include <cuda_runtime.h>
#include <stdint.h>
#include <math.h>

#define THREADS 256
#define BATCH 32
#define SPIX (768*768)            // 589824 pixels per sample
#define S2 (SPIX/2)               // 294912 2-pixel units per sample
#define NPAIR (BATCH*2)           // 64 (sample, channel) pairs
#define NBINS 4096
#define CHUNK 9216                // pixels per block
#define J_PER_BLK (CHUNK/2)       // 4608 2-pixel units per block (= 18*256)
#define BLOCKS_PER_SAMPLE (SPIX/CHUNK)   // 64
#define NBLOCKS (BATCH*BLOCKS_PER_SAMPLE) // 2048
#define P1_BLOCKS 512             // 1/8 of chunks, each split over 2 blocks
#define POS_THR 0.1f

// ---------------- scratch (static __device__, no allocations) ----------------
__device__ unsigned int g_pos_cnt[NPAIR];    // sampled (1/8) positive counts
__device__ unsigned int g_pos_cnt2[NPAIR];   // exact positive counts (pass2)
__device__ unsigned int g_s_hist[NPAIR*NBINS];
__device__ unsigned int g_lo_key[NPAIR];
__device__ unsigned int g_hi_key[NPAIR];
__device__ int          g_shift[NPAIR];
__device__ unsigned int g_above_cnt[NPAIR];
__device__ double       g_above_sum[NPAIR];
__device__ double       g_pos_sum[NPAIR];
__device__ unsigned int g_h2_cnt[NPAIR*NBINS];
__device__ float        g_h2_sum[NPAIR*NBINS];

// ---------------- reductions ----------------
__device__ __forceinline__ float blockSumF(float v, volatile float* sh) {
#pragma unroll
    for (int o = 16; o; o >>= 1) v += __shfl_down_sync(0xFFFFFFFFu, v, o);
    int w = threadIdx.x >> 5;
    __syncthreads();
    if ((threadIdx.x & 31) == 0) sh[w] = v;
    __syncthreads();
    float r = (threadIdx.x < 8) ? sh[threadIdx.x] : 0.f;
    if (threadIdx.x < 32) {
#pragma unroll
        for (int o = 4; o; o >>= 1) r += __shfl_down_sync(0xFFFFFFFFu, r, o);
    }
    return r;
}

__device__ __forceinline__ int blockSumI(int v, volatile int* sh) {
#pragma unroll
    for (int o = 16; o; o >>= 1) v += __shfl_down_sync(0xFFFFFFFFu, v, o);
    int w = threadIdx.x >> 5;
    __syncthreads();
    if ((threadIdx.x & 31) == 0) sh[w] = v;
    __syncthreads();
    int r = (threadIdx.x < 8) ? sh[threadIdx.x] : 0;
    if (threadIdx.x < 32) {
#pragma unroll
        for (int o = 4; o; o >>= 1) r += __shfl_down_sync(0xFFFFFFFFu, r, o);
    }
    return r;
}

// ---------------- kernel 0: zero scratch + output ----------------
__global__ void k_zero(float* out) {
    int i = blockIdx.x * blockDim.x + threadIdx.x;
    if (i < NPAIR * NBINS) {
        g_s_hist[i] = 0u;
        g_h2_cnt[i] = 0u;
        g_h2_sum[i] = 0.f;
    }
    if (i < NPAIR) {
        g_pos_cnt[i] = 0u;
        g_pos_cnt2[i] = 0u;
        g_above_cnt[i] = 0u;
        g_above_sum[i] = 0.0;
        g_pos_sum[i] = 0.0;
    }
    if (i == 0) out[0] = 0.f;
}

// ---------------- kernel 1: sampled pos counts + sampled negative histogram ----------------
// 512 blocks: 8 sampled chunks per sample (1/8 of labels), each chunk split over
// 2 blocks (9 iters each) for latency hiding. Pred read every 3rd iter -> 1/24 of pixels.
__global__ void __launch_bounds__(THREADS) k_pass1(
    const float4* __restrict__ pred4,
    const float2* __restrict__ reg2,
    const float2* __restrict__ aff2)
{
    int blk = blockIdx.x;
    int s = blk >> 4;                 // 16 blocks per sample
    int h = blk & 15;
    int ci = (h >> 1) << 3;           // chunks 0,8,16,...,56
    int half = h & 1;
    int base = s * S2 + ci * J_PER_BLK + half * (J_PER_BLK / 2);
    int tid = threadIdx.x;

    unsigned int* h0 = g_s_hist + (2 * s) * NBINS;
    unsigned int* h1 = g_s_hist + (2 * s + 1) * NBINS;

    int c0 = 0, c1 = 0;
    for (int it = 0; it < 9; ++it) {
        int idx = base + it * THREADS + tid;
        float2 rg = reg2[idx];
        float2 af = aff2[idx];
        c0 += (rg.x >= POS_THR) + (rg.y >= POS_THR);
        c1 += (af.x >= POS_THR) + (af.y >= POS_THR);
        if (it % 3 == 0) {
            float4 pr = pred4[idx];
            float d;
            if (rg.x < POS_THR) { d = pr.x - rg.x; float l = d * d; atomicAdd(&h0[__float_as_uint(l) >> 20], 1u); }
            if (af.x < POS_THR) { d = pr.y - af.x; float l = d * d; atomicAdd(&h1[__float_as_uint(l) >> 20], 1u); }
            if (rg.y < POS_THR) { d = pr.z - rg.y; float l = d * d; atomicAdd(&h0[__float_as_uint(l) >> 20], 1u); }
            if (af.y < POS_THR) { d = pr.w - af.y; float l = d * d; atomicAdd(&h1[__float_as_uint(l) >> 20], 1u); }
        }
    }
    __shared__ int shi[8];
    int t0 = blockSumI(c0, shi);
    if (tid == 0 && t0) atomicAdd(&g_pos_cnt[2 * s], (unsigned)t0);
    int t1 = blockSumI(c1, shi);
    if (tid == 0 && t1) atomicAdd(&g_pos_cnt[2 * s + 1], (unsigned)t1);
}

// ---------------- kernel 2: pick bracket [lo_key, hi_key) from sample ----------------
__global__ void __launch_bounds__(THREADS) k_select()
{
    int pair = blockIdx.x;
    int tid = threadIdx.x;
    const unsigned int* h = g_s_hist + pair * NBINS;

    unsigned lc[16]; unsigned cnt = 0;
#pragma unroll
    for (int i = 0; i < 16; ++i) { lc[i] = h[NBINS - 1 - (tid * 16 + i)]; cnt += lc[i]; }

    __shared__ unsigned scnt[THREADS];
    scnt[tid] = cnt; __syncthreads();
    for (int off = 1; off < THREADS; off <<= 1) {
        unsigned c2 = (tid >= off) ? scnt[tid - off] : 0u;
        __syncthreads();
        scnt[tid] += c2;
        __syncthreads();
    }

    __shared__ long long sh_hi_r, sh_lo_r;
    __shared__ int sh_hb, sh_lb, sh_kpos;
    if (tid == 0) {
        double p_hat = 8.0 * (double)g_pos_cnt[pair];       // labels sampled at 1/8
        double nn_hat = (double)SPIX - p_hat;
        if (nn_hat < 1.0) nn_hat = 1.0;
        long long m = (long long)scnt[THREADS - 1];
        long long hi_r = 1, lo_r = (m > 0) ? m : 1;
        int kpos = 1;
        if (m > 0) {
            double scale = nn_hat / (double)m;              // ~24
            if (p_hat < 10000.0) {
                double k_up = 3.0 * (p_hat + 8.0 * sqrt(7.0 * p_hat + 1.0) + 300.0);
                if (k_up < 500.0) k_up = 500.0;
                double lr = k_up / scale + 8.0 * sqrt(0.25 * (double)m) + 192.0;
                hi_r = 1;
                lo_r = (lr >= (double)m) ? m : (long long)(lr + 1.0);
            } else {
                double k_hat = 3.0 * p_hat;
                if (k_hat > nn_hat) k_hat = nn_hat;
                double ks = k_hat / scale;                  // target sample rank
                double delta = 16.0 * sqrt(p_hat) / scale   // sampled-p uncertainty
                             + 8.0 * sqrt(0.25 * (double)m) // sample-rank noise
                             + 192.0;
                double a = ks - delta, b2 = ks + delta;
                hi_r = (a < 1.0) ? 1 : (long long)a;
                lo_r = (b2 >= (double)m) ? m : (long long)(b2 + 1.0);
                if (lo_r < hi_r) lo_r = hi_r;
            }
        } else {
            kpos = 0;
        }
        sh_hi_r = hi_r; sh_lo_r = lo_r; sh_kpos = kpos;
        sh_hb = NBINS - 1; sh_lb = 0;
    }
    __syncthreads();
    long long hi_r = sh_hi_r, lo_r = sh_lo_r;
    long long ex = (long long)(scnt[tid] - cnt), inc = (long long)scnt[tid];
    if (ex < hi_r && hi_r <= inc) {
        long long cc = ex;
#pragma unroll
        for (int i = 0; i < 16; ++i) { cc += lc[i]; if (hi_r <= cc) { sh_hb = NBINS - 1 - (tid * 16 + i); break; } }
    }
    if (ex < lo_r && lo_r <= inc) {
        long long cc = ex;
#pragma unroll
        for (int i = 0; i < 16; ++i) { cc += lc[i]; if (lo_r <= cc) { sh_lb = NBINS - 1 - (tid * 16 + i); break; } }
    }
    __syncthreads();
    if (tid == 0) {
        unsigned lo_key; unsigned long long hk; int sft = 8;
        if (sh_kpos) {
            int hi_bin = sh_hb + 3; if (hi_bin > NBINS - 1) hi_bin = NBINS - 1;
            int lo_bin = sh_lb - 3; if (lo_bin < 0) lo_bin = 0;
            if (lo_bin > hi_bin) lo_bin = hi_bin;
            int span = hi_bin - lo_bin + 1;
            while (((long long)span << 20) > (4096LL << sft)) sft++;
            lo_key = ((unsigned)lo_bin) << 20;
            hk = (unsigned long long)lo_key + (4096ULL << sft);
            if (hk > 0x7F800000ULL) hk = 0x7F800000ULL;
        } else {
            lo_key = 0u; hk = 0ULL;   // no sampled negatives: everything "above"
        }
        g_lo_key[pair] = lo_key;
        g_hi_key[pair] = (unsigned)hk;
        g_shift[pair] = sft;
    }
}

// ---------------- kernel 3: full pass ----------------
// Float compares: for non-negative finite floats, (bits(l) >= key) == (l >= uint_as_float(key)).
__device__ __forceinline__ void proc_px(float pc, float lab,
    float hif, float lof, unsigned lo, int sft,
    float& psum, int& pcn, float& asum, int& acnt,
    unsigned* __restrict__ hcnt, float* __restrict__ hsum)
{
    float d = pc - lab;
    float l = d * d;
    if (lab >= POS_THR) {
        pcn++;
        psum += l;
    } else if (l >= hif) {
        acnt++;
        asum += l;
    } else if (l >= lof) {
        unsigned b = (__float_as_uint(l) - lo) >> sft;
        if (b > 4095u) b = 4095u;
        atomicAdd(hcnt + b, 1u);
        atomicAdd(hsum + b, l);
    }
}

__global__ void __launch_bounds__(THREADS) k_pass2(
    const float4* __restrict__ pred4,
    const float2* __restrict__ reg2,
    const float2* __restrict__ aff2)
{
    int blk = blockIdx.x;
    int s = blk / BLOCKS_PER_SAMPLE;
    int chunk = blk - s * BLOCKS_PER_SAMPLE;
    int base = s * S2 + chunk * J_PER_BLK;
    int tid = threadIdx.x;

    unsigned lo0 = g_lo_key[2 * s]; int sf0 = g_shift[2 * s];
    unsigned lo1 = g_lo_key[2 * s + 1]; int sf1 = g_shift[2 * s + 1];
    float lof0 = __uint_as_float(lo0), hif0 = __uint_as_float(g_hi_key[2 * s]);
    float lof1 = __uint_as_float(lo1), hif1 = __uint_as_float(g_hi_key[2 * s + 1]);
    unsigned* hc0 = g_h2_cnt + (2 * s) * NBINS;     float* hs0 = g_h2_sum + (2 * s) * NBINS;
    unsigned* hc1 = g_h2_cnt + (2 * s + 1) * NBINS; float* hs1 = g_h2_sum + (2 * s + 1) * NBINS;

    float ps0 = 0.f, ps1 = 0.f, as0 = 0.f, as1 = 0.f;
    int ac0 = 0, ac1 = 0, pc0 = 0, pc1 = 0;

#pragma unroll 3
    for (int it = 0; it < 18; it += 2) {
        int i0 = base + it * THREADS + tid;
        int i1 = i0 + THREADS;
        // all six loads fully coalesced, named scalars (no local-memory arrays)
        float4 pr0 = pred4[i0];
        float4 pr1 = pred4[i1];
        float2 rg0 = reg2[i0];
        float2 rg1 = reg2[i1];
        float2 af0 = aff2[i0];
        float2 af1 = aff2[i1];

        proc_px(pr0.x, rg0.x, hif0, lof0, lo0, sf0, ps0, pc0, as0, ac0, hc0, hs0);
        proc_px(pr0.y, af0.x, hif1, lof1, lo1, sf1, ps1, pc1, as1, ac1, hc1, hs1);
        proc_px(pr0.z, rg0.y, hif0, lof0, lo0, sf0, ps0, pc0, as0, ac0, hc0, hs0);
        proc_px(pr0.w, af0.y, hif1, lof1, lo1, sf1, ps1, pc1, as1, ac1, hc1, hs1);
        proc_px(pr1.x, rg1.x, hif0, lof0, lo0, sf0, ps0, pc0, as0, ac0, hc0, hs0);
        proc_px(pr1.y, af1.x, hif1, lof1, lo1, sf1, ps1, pc1, as1, ac1, hc1, hs1);
        proc_px(pr1.z, rg1.y, hif0, lof0, lo0, sf0, ps0, pc0, as0, ac0, hc0, hs0);
        proc_px(pr1.w, af1.y, hif1, lof1, lo1, sf1, ps1, pc1, as1, ac1, hc1, hs1);
    }

    __shared__ float shf[8];
    __shared__ int shi[8];
    float t;
    t = blockSumF(ps0, shf); if (tid == 0 && t != 0.f) atomicAdd(&g_pos_sum[2 * s], (double)t);
    t = blockSumF(ps1, shf); if (tid == 0 && t != 0.f) atomicAdd(&g_pos_sum[2 * s + 1], (double)t);
    t = blockSumF(as0, shf); if (tid == 0 && t != 0.f) atomicAdd(&g_above_sum[2 * s], (double)t);
    t = blockSumF(as1, shf); if (tid == 0 && t != 0.f) atomicAdd(&g_above_sum[2 * s + 1], (double)t);
    int ti;
    ti = blockSumI(ac0, shi); if (tid == 0 && ti) atomicAdd(&g_above_cnt[2 * s], (unsigned)ti);
    ti = blockSumI(ac1, shi); if (tid == 0 && ti) atomicAdd(&g_above_cnt[2 * s + 1], (unsigned)ti);
    ti = blockSumI(pc0, shi); if (tid == 0 && ti) atomicAdd(&g_pos_cnt2[2 * s], (unsigned)ti);
    ti = blockSumI(pc1, shi); if (tid == 0 && ti) atomicAdd(&g_pos_cnt2[2 * s + 1], (unsigned)ti);
}

// ---------------- kernel 4: resolve threshold bin, produce final scalar ----------------
__global__ void __launch_bounds__(THREADS) k_final(float* out)
{
    int pair = blockIdx.x;
    int tid = threadIdx.x;
    const unsigned* hc = g_h2_cnt + pair * NBINS;
    const float* hs = g_h2_sum + pair * NBINS;

    unsigned lc[16]; float lsv[16];
    unsigned cnt = 0; float fsum = 0.f;
#pragma unroll
    for (int i = 0; i < 16; ++i) {
        int b = NBINS - 1 - (tid * 16 + i);
        lc[i] = hc[b]; lsv[i] = hs[b];
        cnt += lc[i]; fsum += lsv[i];
    }
    __shared__ unsigned long long scnt[THREADS];
    __shared__ double ssum[THREADS];
    scnt[tid] = cnt; ssum[tid] = (double)fsum;
    __syncthreads();
    for (int off = 1; off < THREADS; off <<= 1) {
        unsigned long long c2 = 0; double s2 = 0;
        if (tid >= off) { c2 = scnt[tid - off]; s2 = ssum[tid - off]; }
        __syncthreads();
        scnt[tid] += c2; ssum[tid] += s2;
        __syncthreads();
    }

    long long p = (long long)g_pos_cnt2[pair];           // exact
    long long nn = (long long)SPIX - p;
    long long k = (p > 0) ? ((nn < 3 * p) ? nn : 3 * p) : 500LL;
    if (k > nn) k = nn;
    if (k < 0) k = 0;

    long long above = (long long)g_above_cnt[pair];
    double above_sum = g_above_sum[pair];
    long long r = k - above;
    long long total = (long long)scnt[THREADS - 1];

    __shared__ double res;
    if (tid == 0) {
        if (r <= 0) res = (above > 0) ? above_sum * (double)k / (double)above : 0.0;
        else if (r > total) res = above_sum + ssum[THREADS - 1];
    }
    if (r > 0 && r <= total) {
        long long ex = (long long)(scnt[tid] - cnt);
        if (ex < r && r <= (long long)scnt[tid]) {
            long long cc = ex;
            double ss = ssum[tid] - (double)fsum;
#pragma unroll
            for (int i = 0; i < 16; ++i) {
                if (r <= cc + (long long)lc[i]) {
                    double avg = lc[i] ? (double)lsv[i] / (double)lc[i] : 0.0;
                    res = above_sum + ss + (double)(r - cc) * avg;
                    break;
                }
                cc += lc[i]; ss += (double)lsv[i];
            }
        }
    }
    __syncthreads();
    if (tid == 0) {
        double nega = (k > 0) ? res / (double)k : 0.0;
        double posi = (p > 0) ? g_pos_sum[pair] / (double)p : 0.0;
        atomicAdd(out, (float)((posi + nega) / (double)BATCH));
    }
}

// ---------------- launcher ----------------
extern "C" void kernel_launch(void* const* d_in, const int* in_sizes, int n_in,
                              void* d_out, int out_size)
{
    const int predN = BATCH * SPIX * 2;
    const float* pred = nullptr;
    const float* reg = nullptr;
    const float* aff = nullptr;
    for (int i = 0; i < n_in; i++) {
        if (in_sizes[i] == predN && !pred) pred = (const float*)d_in[i];
        else if (!reg) reg = (const float*)d_in[i];
        else if (!aff) aff = (const float*)d_in[i];
    }
    float* out = (float*)d_out;

    k_zero<<<(NPAIR * NBINS + THREADS - 1) / THREADS, THREADS>>>(out);
    k_pass1<<<P1_BLOCKS, THREADS>>>((const float4*)pred, (const float2*)reg, (const float2*)aff);
    k_select<<<NPAIR, THREADS>>>();
    k_pass2<<<NBLOCKS, THREADS>>>((const float4*)pred, (const float2*)reg, (const float2*)aff);
    k_final<<<NPAIR, THREADS>>>(out);
}

// round 9
// speedup vs baseline: 1.8573x; 1.7700x over previous
#include <cuda_runtime.h>
#include <stdint.h>
#include <math.h>

#define THREADS 256
#define BATCH 32
#define SPIX (768*768)            // 589824 pixels per sample
#define S2 (SPIX/2)               // 294912 2-pixel units per sample
#define NPAIR (BATCH*2)           // 64 (sample, channel) pairs
#define NBINS 4096
#define CHUNK 9216                // pixels per block
#define J_PER_BLK (CHUNK/2)       // 4608 2-pixel units per block (= 18*256)
#define BLOCKS_PER_SAMPLE (SPIX/CHUNK)   // 64
#define NBLOCKS (BATCH*BLOCKS_PER_SAMPLE) // 2048
#define P1_BLOCKS (NBLOCKS/4)     // 512: sample 1/4 of chunks in pass1
#define POS_THR 0.1f

// ---------------- scratch (static __device__, no allocations) ----------------
__device__ unsigned int g_pos_cnt[NPAIR];    // sampled (1/4) positive counts
__device__ unsigned int g_pos_cnt2[NPAIR];   // exact positive counts (pass2)
__device__ unsigned int g_s_hist[NPAIR*NBINS];
__device__ unsigned int g_lo_key[NPAIR];
__device__ unsigned int g_hi_key[NPAIR];
__device__ int          g_shift[NPAIR];
__device__ unsigned int g_above_cnt[NPAIR];
__device__ double       g_above_sum[NPAIR];
__device__ double       g_pos_sum[NPAIR];
__device__ unsigned int g_h2_cnt[NPAIR*NBINS];   // refined bracket histogram (counts only)

// ---------------- reductions ----------------
__device__ __forceinline__ float blockSumF(float v, volatile float* sh) {
#pragma unroll
    for (int o = 16; o; o >>= 1) v += __shfl_down_sync(0xFFFFFFFFu, v, o);
    int w = threadIdx.x >> 5;
    __syncthreads();
    if ((threadIdx.x & 31) == 0) sh[w] = v;
    __syncthreads();
    float r = (threadIdx.x < 8) ? sh[threadIdx.x] : 0.f;
    if (threadIdx.x < 32) {
#pragma unroll
        for (int o = 4; o; o >>= 1) r += __shfl_down_sync(0xFFFFFFFFu, r, o);
    }
    return r;
}

__device__ __forceinline__ int blockSumI(int v, volatile int* sh) {
#pragma unroll
    for (int o = 16; o; o >>= 1) v += __shfl_down_sync(0xFFFFFFFFu, v, o);
    int w = threadIdx.x >> 5;
    __syncthreads();
    if ((threadIdx.x & 31) == 0) sh[w] = v;
    __syncthreads();
    int r = (threadIdx.x < 8) ? sh[threadIdx.x] : 0;
    if (threadIdx.x < 32) {
#pragma unroll
        for (int o = 4; o; o >>= 1) r += __shfl_down_sync(0xFFFFFFFFu, r, o);
    }
    return r;
}

// ---------------- kernel 0: zero scratch + output ----------------
__global__ void k_zero(float* out) {
    int i = blockIdx.x * blockDim.x + threadIdx.x;
    if (i < NPAIR * NBINS) {
        g_s_hist[i] = 0u;
        g_h2_cnt[i] = 0u;
    }
    if (i < NPAIR) {
        g_pos_cnt[i] = 0u;
        g_pos_cnt2[i] = 0u;
        g_above_cnt[i] = 0u;
        g_above_sum[i] = 0.0;
        g_pos_sum[i] = 0.0;
    }
    if (i == 0) out[0] = 0.f;
}

// ---------------- kernel 1: sampled pos counts + sampled negative histogram ----------------
// 512 blocks = 1/4 of chunks. Labels of sampled chunks read fully (p sampled at 1/4);
// pred read every 3rd unit-iter (histogram samples 1/12 of pixels).
__global__ void __launch_bounds__(THREADS) k_pass1(
    const float4* __restrict__ pred4,
    const float2* __restrict__ reg2,
    const float2* __restrict__ aff2)
{
    int blk = blockIdx.x;
    int s = blk >> 4;                 // 16 sampled chunks per sample
    int ci = (blk & 15) << 2;         // chunks 0,4,8,...,60
    int base = s * S2 + ci * J_PER_BLK;
    int tid = threadIdx.x;

    unsigned int* h0 = g_s_hist + (2 * s) * NBINS;
    unsigned int* h1 = g_s_hist + (2 * s + 1) * NBINS;

    int c0 = 0, c1 = 0;
    for (int it = 0; it < 18; ++it) {
        int idx = base + it * THREADS + tid;
        float2 rg = reg2[idx];
        float2 af = aff2[idx];
        c0 += (rg.x >= POS_THR) + (rg.y >= POS_THR);
        c1 += (af.x >= POS_THR) + (af.y >= POS_THR);
        if (it % 3 == 0) {
            float4 pr = pred4[idx];
            float d;
            if (rg.x < POS_THR) { d = pr.x - rg.x; float l = d * d; atomicAdd(&h0[__float_as_uint(l) >> 20], 1u); }
            if (af.x < POS_THR) { d = pr.y - af.x; float l = d * d; atomicAdd(&h1[__float_as_uint(l) >> 20], 1u); }
            if (rg.y < POS_THR) { d = pr.z - rg.y; float l = d * d; atomicAdd(&h0[__float_as_uint(l) >> 20], 1u); }
            if (af.y < POS_THR) { d = pr.w - af.y; float l = d * d; atomicAdd(&h1[__float_as_uint(l) >> 20], 1u); }
        }
    }
    __shared__ int shi[8];
    int t0 = blockSumI(c0, shi);
    if (tid == 0 && t0) atomicAdd(&g_pos_cnt[2 * s], (unsigned)t0);
    int t1 = blockSumI(c1, shi);
    if (tid == 0 && t1) atomicAdd(&g_pos_cnt[2 * s + 1], (unsigned)t1);
}

// ---------------- kernel 2: pick bracket [lo_key, hi_key) from sample ----------------
__global__ void __launch_bounds__(THREADS) k_select()
{
    int pair = blockIdx.x;
    int tid = threadIdx.x;
    const unsigned int* h = g_s_hist + pair * NBINS;

    unsigned lc[16]; unsigned cnt = 0;
#pragma unroll
    for (int i = 0; i < 16; ++i) { lc[i] = h[NBINS - 1 - (tid * 16 + i)]; cnt += lc[i]; }

    __shared__ unsigned scnt[THREADS];
    scnt[tid] = cnt; __syncthreads();
    for (int off = 1; off < THREADS; off <<= 1) {
        unsigned c2 = (tid >= off) ? scnt[tid - off] : 0u;
        __syncthreads();
        scnt[tid] += c2;
        __syncthreads();
    }

    __shared__ long long sh_hi_r, sh_lo_r;
    __shared__ int sh_hb, sh_lb, sh_kpos;
    if (tid == 0) {
        double p_hat = 4.0 * (double)g_pos_cnt[pair];       // labels sampled at 1/4
        double nn_hat = (double)SPIX - p_hat;
        if (nn_hat < 1.0) nn_hat = 1.0;
        long long m = (long long)scnt[THREADS - 1];
        long long hi_r = 1, lo_r = (m > 0) ? m : 1;
        int kpos = 1;
        if (m > 0) {
            double scale = nn_hat / (double)m;              // ~12
            if (p_hat < 10000.0) {
                double k_up = 3.0 * (p_hat + 6.0 * sqrt(3.0 * p_hat + 1.0) + 200.0);
                if (k_up < 500.0) k_up = 500.0;
                double lr = k_up / scale + 6.0 * sqrt(0.25 * (double)m) + 128.0;
                hi_r = 1;
                lo_r = (lr >= (double)m) ? m : (long long)(lr + 1.0);
            } else {
                double k_hat = 3.0 * p_hat;
                if (k_hat > nn_hat) k_hat = nn_hat;
                double ks = k_hat / scale;                  // target sample rank
                double delta = 12.0 * sqrt(p_hat) / scale   // sampled-p uncertainty
                             + 6.0 * sqrt(0.25 * (double)m) // sample-rank noise
                             + 128.0;
                double a = ks - delta, b2 = ks + delta;
                hi_r = (a < 1.0) ? 1 : (long long)a;
                lo_r = (b2 >= (double)m) ? m : (long long)(b2 + 1.0);
                if (lo_r < hi_r) lo_r = hi_r;
            }
        } else {
            kpos = 0;
        }
        sh_hi_r = hi_r; sh_lo_r = lo_r; sh_kpos = kpos;
        sh_hb = NBINS - 1; sh_lb = 0;
    }
    __syncthreads();
    long long hi_r = sh_hi_r, lo_r = sh_lo_r;
    long long ex = (long long)(scnt[tid] - cnt), inc = (long long)scnt[tid];
    if (ex < hi_r && hi_r <= inc) {
        long long cc = ex;
#pragma unroll
        for (int i = 0; i < 16; ++i) { cc += lc[i]; if (hi_r <= cc) { sh_hb = NBINS - 1 - (tid * 16 + i); break; } }
    }
    if (ex < lo_r && lo_r <= inc) {
        long long cc = ex;
#pragma unroll
        for (int i = 0; i < 16; ++i) { cc += lc[i]; if (lo_r <= cc) { sh_lb = NBINS - 1 - (tid * 16 + i); break; } }
    }
    __syncthreads();
    if (tid == 0) {
        unsigned lo_key; unsigned long long hk; int sft = 8;
        if (sh_kpos) {
            int hi_bin = sh_hb + 2; if (hi_bin > NBINS - 1) hi_bin = NBINS - 1;
            int lo_bin = sh_lb - 2; if (lo_bin < 0) lo_bin = 0;
            if (lo_bin > hi_bin) lo_bin = hi_bin;
            int span = hi_bin - lo_bin + 1;
            while (((long long)span << 20) > (4096LL << sft)) sft++;
            lo_key = ((unsigned)lo_bin) << 20;
            hk = (unsigned long long)lo_key + (4096ULL << sft);
            if (hk > 0x7F800000ULL) hk = 0x7F800000ULL;
        } else {
            lo_key = 0xFFFFFFFFu; hk = 0xFFFFFFFFULL;   // nothing matches
        }
        g_lo_key[pair] = lo_key;
        g_hi_key[pair] = (unsigned)hk;
        g_shift[pair] = sft;
    }
}

// ---------------- kernel 3: full pass ----------------
__device__ __forceinline__ void proc_px(float pc, float lab,
    unsigned lo, unsigned hi, int sft,
    float& psum, int& pcn, float& asum, int& acnt,
    unsigned* __restrict__ hcnt)
{
    float d = pc - lab;
    float l = d * d;
    if (lab >= POS_THR) {
        pcn++;
        psum += l;
    } else {
        unsigned u = __float_as_uint(l);
        if (u >= hi) { acnt++; asum += l; }
        else if (u >= lo) {
            unsigned b = (u - lo) >> sft;
            if (b > 4095u) b = 4095u;
            atomicAdd(hcnt + b, 1u);       // count-only: value reconstructed in k_final
        }
    }
}

__global__ void __launch_bounds__(THREADS) k_pass2(
    const float4* __restrict__ pred4,
    const float2* __restrict__ reg2,
    const float2* __restrict__ aff2)
{
    int blk = blockIdx.x;
    int s = blk / BLOCKS_PER_SAMPLE;
    int chunk = blk - s * BLOCKS_PER_SAMPLE;
    int base = s * S2 + chunk * J_PER_BLK;
    int tid = threadIdx.x;

    unsigned lo0 = g_lo_key[2 * s], hi0 = g_hi_key[2 * s]; int sf0 = g_shift[2 * s];
    unsigned lo1 = g_lo_key[2 * s + 1], hi1 = g_hi_key[2 * s + 1]; int sf1 = g_shift[2 * s + 1];
    unsigned* hc0 = g_h2_cnt + (2 * s) * NBINS;
    unsigned* hc1 = g_h2_cnt + (2 * s + 1) * NBINS;

    float ps0 = 0.f, ps1 = 0.f, as0 = 0.f, as1 = 0.f;
    int ac0 = 0, ac1 = 0, pc0 = 0, pc1 = 0;

#pragma unroll 3
    for (int it = 0; it < 18; it += 2) {
        int i0 = base + it * THREADS + tid;
        int i1 = i0 + THREADS;
        // all six loads fully coalesced, named scalars
        float4 pr0 = pred4[i0];
        float4 pr1 = pred4[i1];
        float2 rg0 = reg2[i0];
        float2 rg1 = reg2[i1];
        float2 af0 = aff2[i0];
        float2 af1 = aff2[i1];

        proc_px(pr0.x, rg0.x, lo0, hi0, sf0, ps0, pc0, as0, ac0, hc0);
        proc_px(pr0.y, af0.x, lo1, hi1, sf1, ps1, pc1, as1, ac1, hc1);
        proc_px(pr0.z, rg0.y, lo0, hi0, sf0, ps0, pc0, as0, ac0, hc0);
        proc_px(pr0.w, af0.y, lo1, hi1, sf1, ps1, pc1, as1, ac1, hc1);
        proc_px(pr1.x, rg1.x, lo0, hi0, sf0, ps0, pc0, as0, ac0, hc0);
        proc_px(pr1.y, af1.x, lo1, hi1, sf1, ps1, pc1, as1, ac1, hc1);
        proc_px(pr1.z, rg1.y, lo0, hi0, sf0, ps0, pc0, as0, ac0, hc0);
        proc_px(pr1.w, af1.y, lo1, hi1, sf1, ps1, pc1, as1, ac1, hc1);
    }

    __shared__ float shf[8];
    __shared__ int shi[8];
    float t;
    t = blockSumF(ps0, shf); if (tid == 0 && t != 0.f) atomicAdd(&g_pos_sum[2 * s], (double)t);
    t = blockSumF(ps1, shf); if (tid == 0 && t != 0.f) atomicAdd(&g_pos_sum[2 * s + 1], (double)t);
    t = blockSumF(as0, shf); if (tid == 0 && t != 0.f) atomicAdd(&g_above_sum[2 * s], (double)t);
    t = blockSumF(as1, shf); if (tid == 0 && t != 0.f) atomicAdd(&g_above_sum[2 * s + 1], (double)t);
    int ti;
    ti = blockSumI(ac0, shi); if (tid == 0 && ti) atomicAdd(&g_above_cnt[2 * s], (unsigned)ti);
    ti = blockSumI(ac1, shi); if (tid == 0 && ti) atomicAdd(&g_above_cnt[2 * s + 1], (unsigned)ti);
    ti = blockSumI(pc0, shi); if (tid == 0 && ti) atomicAdd(&g_pos_cnt2[2 * s], (unsigned)ti);
    ti = blockSumI(pc1, shi); if (tid == 0 && ti) atomicAdd(&g_pos_cnt2[2 * s + 1], (unsigned)ti);
}

// ---------------- kernel 4: resolve threshold bin, produce final scalar ----------------
// Bracket bin b covers keys [lo + b*2^sft, lo + (b+1)*2^sft); approximate every value
// in b by the bin-center float (<= 2^-12 relative half-width -> ~1e-6 on the result).
__global__ void __launch_bounds__(THREADS) k_final(float* out)
{
    int pair = blockIdx.x;
    int tid = threadIdx.x;
    const unsigned* hc = g_h2_cnt + pair * NBINS;
    unsigned lo = g_lo_key[pair];
    int sft = g_shift[pair];
    unsigned half = 1u << (sft - 1);

    unsigned lc[16]; float lv[16];
    unsigned cnt = 0; double fsum = 0.0;
#pragma unroll
    for (int i = 0; i < 16; ++i) {
        int b = NBINS - 1 - (tid * 16 + i);
        lc[i] = hc[b];
        lv[i] = __uint_as_float(lo + ((unsigned)b << sft) + half);
        cnt += lc[i]; fsum += (double)lc[i] * (double)lv[i];
    }
    __shared__ unsigned long long scnt[THREADS];
    __shared__ double ssum[THREADS];
    scnt[tid] = cnt; ssum[tid] = fsum;
    __syncthreads();
    for (int off = 1; off < THREADS; off <<= 1) {
        unsigned long long c2 = 0; double s2 = 0;
        if (tid >= off) { c2 = scnt[tid - off]; s2 = ssum[tid - off]; }
        __syncthreads();
        scnt[tid] += c2; ssum[tid] += s2;
        __syncthreads();
    }

    long long p = (long long)g_pos_cnt2[pair];           // exact
    long long nn = (long long)SPIX - p;
    long long k = (p > 0) ? ((nn < 3 * p) ? nn : 3 * p) : 500LL;
    if (k > nn) k = nn;
    if (k < 0) k = 0;

    long long above = (long long)g_above_cnt[pair];
    double above_sum = g_above_sum[pair];
    long long r = k - above;
    long long total = (long long)scnt[THREADS - 1];

    __shared__ double res;
    if (tid == 0) {
        if (r <= 0) res = (above > 0) ? above_sum * (double)k / (double)above : 0.0;
        else if (r > total) res = above_sum + ssum[THREADS - 1];
    }
    if (r > 0 && r <= total) {
        long long ex = (long long)(scnt[tid] - cnt);
        if (ex < r && r <= (long long)scnt[tid]) {
            long long cc = ex;
            double ss = ssum[tid] - fsum;
#pragma unroll
            for (int i = 0; i < 16; ++i) {
                if (r <= cc + (long long)lc[i]) {
                    res = above_sum + ss + (double)(r - cc) * (double)lv[i];
                    break;
                }
                cc += lc[i]; ss += (double)lc[i] * (double)lv[i];
            }
        }
    }
    __syncthreads();
    if (tid == 0) {
        double nega = (k > 0) ? res / (double)k : 0.0;
        double posi = (p > 0) ? g_pos_sum[pair] / (double)p : 0.0;
        atomicAdd(out, (float)((posi + nega) / (double)BATCH));
    }
}

// ---------------- launcher ----------------
extern "C" void kernel_launch(void* const* d_in, const int* in_sizes, int n_in,
                              void* d_out, int out_size)
{
    const int predN = BATCH * SPIX * 2;
    const float* pred = nullptr;
    const float* reg = nullptr;
    const float* aff = nullptr;
    for (int i = 0; i < n_in; i++) {
        if (in_sizes[i] == predN && !pred) pred = (const float*)d_in[i];
        else if (!reg) reg = (const float*)d_in[i];
        else if (!aff) aff = (const float*)d_in[i];
    }
    float* out = (float*)d_out;

    k_zero<<<(NPAIR * NBINS + THREADS - 1) / THREADS, THREADS>>>(out);
    k_pass1<<<P1_BLOCKS, THREADS>>>((const float4*)pred, (const float2*)reg, (const float2*)aff);
    k_select<<<NPAIR, THREADS>>>();
    k_pass2<<<NBLOCKS, THREADS>>>((const float4*)pred, (const float2*)reg, (const float2*)aff);
    k_final<<<NPAIR, THREADS>>>(out);
}